// round 9
// baseline (speedup 1.0000x reference)
#include <cuda_runtime.h>
#include <cuda_bf16.h>
#include <cstdint>

#define NROWS 16384
#define DD    128
#define BM    64
#define BN    128
#define NTILES (NROWS / BN)
#define NTHREADS 128

// device globals (allocation-free rule)
__device__ uint8_t g_nx8[NROWS * DD];   // fp8 e4m3 normalized rows (Q/K), row-major
__device__ uint8_t g_xt8[DD * NROWS];   // fp8 e4m3 x transposed (V), d-major

// ---------------------------------------------------------------------------
__device__ __forceinline__ uint32_t smem_u32(const void* p) {
    uint32_t a;
    asm("{ .reg .u64 t; cvta.to.shared.u64 t, %1; cvt.u32.u64 %0, t; }"
        : "=r"(a) : "l"(p));
    return a;
}
__device__ __forceinline__ void cpa16(uint32_t dst, const void* src) {
    asm volatile("cp.async.cg.shared.global [%0], [%1], 16;"
                 :: "r"(dst), "l"(src) : "memory");
}
#define CP_COMMIT() asm volatile("cp.async.commit_group;" ::: "memory")
#define CP_WAIT1()  asm volatile("cp.async.wait_group 1;" ::: "memory")
#define CP_WAIT0()  asm volatile("cp.async.wait_group 0;" ::: "memory")

__device__ __forceinline__ void ldsm4(uint32_t* r, uint32_t addr) {
    asm volatile("ldmatrix.sync.aligned.m8n8.x4.shared.b16 {%0,%1,%2,%3}, [%4];"
        : "=r"(r[0]), "=r"(r[1]), "=r"(r[2]), "=r"(r[3]) : "r"(addr));
}
// fp8 e4m3 MMA, k=32
__device__ __forceinline__ void mma_fp8(float* c, const uint32_t* a,
                                        uint32_t b0, uint32_t b1) {
    asm volatile("mma.sync.aligned.m16n8k32.row.col.f32.e4m3.e4m3.f32 "
        "{%0,%1,%2,%3}, {%4,%5,%6,%7}, {%8,%9}, {%0,%1,%2,%3};"
        : "+f"(c[0]), "+f"(c[1]), "+f"(c[2]), "+f"(c[3])
        : "r"(a[0]), "r"(a[1]), "r"(a[2]), "r"(a[3]), "r"(b0), "r"(b1));
}
// pack 4 floats -> 4 e4m3 bytes (f0 = byte0)
__device__ __forceinline__ uint32_t pack4e4m3(float f0, float f1, float f2, float f3) {
    uint16_t lo, hi;
    asm("cvt.rn.satfinite.e4m3x2.f32 %0, %1, %2;" : "=h"(lo) : "f"(f1), "f"(f0));
    asm("cvt.rn.satfinite.e4m3x2.f32 %0, %1, %2;" : "=h"(hi) : "f"(f3), "f"(f2));
    uint32_t d;
    asm("mov.b32 %0, {%1, %2};" : "=r"(d) : "h"(lo), "h"(hi));
    return d;
}
// Degree-7 Taylor exp, |s| <~ 1.1: rel err < 1e-4, pure FFMA
__device__ __forceinline__ float expp(float s) {
    float p = 1.9841270e-4f;
    p = fmaf(p, s, 1.3888889e-3f);
    p = fmaf(p, s, 8.3333333e-3f);
    p = fmaf(p, s, 4.1666667e-2f);
    p = fmaf(p, s, 1.6666667e-1f);
    p = fmaf(p, s, 0.5f);
    p = fmaf(p, s, 1.0f);
    p = fmaf(p, s, 1.0f);
    return p;
}
// fp8 tile smem layout: row r (0..127) * 128B, 16B chunk c (0..7) swizzled
__device__ __forceinline__ uint32_t toff8(int r, int c) {
    return (uint32_t)(r * 128 + ((c ^ (r & 7)) << 4));
}

#define STG_K(s) ((s) * 32768)
#define STG_V(s) ((s) * 32768 + 16384)
#define SMEM_BYTES 65536

// ---------------------------------------------------------------------------
// Prepass 1: normalized rows -> fp8 (Q/K operand).
// ---------------------------------------------------------------------------
__global__ void prep_kernel(const float* __restrict__ x) {
    int row  = blockIdx.x * 8 + (threadIdx.x >> 5);
    int lane = threadIdx.x & 31;
    float4 v = *(const float4*)(x + (size_t)row * DD + lane * 4);
    float ss = v.x * v.x + v.y * v.y + v.z * v.z + v.w * v.w;
    #pragma unroll
    for (int o = 16; o; o >>= 1) ss += __shfl_xor_sync(0xffffffffu, ss, o);
    float inv = 1.0f / fmaxf(sqrtf(ss), 1e-12f);
    *(uint32_t*)(g_nx8 + (size_t)row * DD + lane * 4) =
        pack4e4m3(v.x * inv, v.y * inv, v.z * inv, v.w * inv);
}

// ---------------------------------------------------------------------------
// Prepass 2: x -> fp8 transposed (V operand, d-major).
// ---------------------------------------------------------------------------
__global__ void trans_kernel(const float* __restrict__ x) {
    __shared__ uint8_t ts[128 * 144];
    int r0 = blockIdx.x * 128;
    int tid = threadIdx.x;
    for (int i = tid; i < 128 * 32; i += 256) {
        int r = i >> 5, c4 = i & 31;
        float4 v = *(const float4*)(x + (size_t)(r0 + r) * DD + c4 * 4);
        uint32_t p = pack4e4m3(v.x, v.y, v.z, v.w);
        ts[(c4 * 4 + 0) * 144 + r] = (uint8_t)(p);
        ts[(c4 * 4 + 1) * 144 + r] = (uint8_t)(p >> 8);
        ts[(c4 * 4 + 2) * 144 + r] = (uint8_t)(p >> 16);
        ts[(c4 * 4 + 3) * 144 + r] = (uint8_t)(p >> 24);
    }
    __syncthreads();
    for (int i = tid; i < 128 * 8; i += 256) {
        int d = i >> 3, ch = i & 7;
        uint4 v = *(const uint4*)(ts + d * 144 + ch * 16);
        *(uint4*)(g_xt8 + (size_t)d * NROWS + r0 + ch * 16) = v;
    }
}

// ---------------------------------------------------------------------------
// Prefetch: K tile (permuted rows within 16-key groups, for fp8 A-frag
// alignment of P) + Vt tile (natural).
// ---------------------------------------------------------------------------
__device__ __forceinline__ void prefetch_tile(int t, uint32_t sb, int tid) {
    if (t < NTILES) {
        uint32_t kb = sb + STG_K(t & 1);
        uint32_t vb = sb + STG_V(t & 1);
        int j0 = t * BN;
        #pragma unroll
        for (int i = 0; i < 8; i++) {
            int idx = tid + i * NTHREADS;        // 1024 = 128 rows x 8 chunks
            int rs = idx >> 3, c = idx & 7;
            int rho = rs & 15;
            // slot rho <- logical key 4*((rho&7)>>1) + 2*(rho>>3) + (rho&1)
            int krow = (rs & ~15) + ((rho & 6) << 1) + ((rho >> 3) << 1) + (rho & 1);
            cpa16(kb + toff8(rs, c), g_nx8 + (size_t)(j0 + krow) * DD + c * 16);
        }
        #pragma unroll
        for (int i = 0; i < 8; i++) {
            int idx = tid + i * NTHREADS;
            int d = idx >> 3, c = idx & 7;
            cpa16(vb + toff8(d, c), g_xt8 + (size_t)d * NROWS + j0 + c * 16);
        }
    }
    CP_COMMIT();
}

// ---------------------------------------------------------------------------
// Fused fp8 attention + LayerNorm. BM=64, 4 warps, 2 CTAs/SM.
// ---------------------------------------------------------------------------
__global__ __launch_bounds__(NTHREADS, 2)
void attn_kernel(const float* __restrict__ x,
                 const float* __restrict__ gamma,
                 const float* __restrict__ beta,
                 float* __restrict__ out) {
    extern __shared__ char smem[];
    uint32_t sb = smem_u32(smem);
    const int tid  = threadIdx.x;
    const int wid  = tid >> 5;
    const int lane = tid & 31;
    const int i0   = blockIdx.x * BM;

    // ---- stage Q tile (64 rows fp8) into stage0 K area; load Q frags ----
    {
        uint32_t qb = sb + STG_K(0);
        #pragma unroll
        for (int i = 0; i < 4; i++) {
            int idx = tid + i * NTHREADS;        // 512 = 64 rows x 8 chunks
            int r = idx >> 3, c = idx & 7;
            cpa16(qb + toff8(r, c), g_nx8 + (size_t)(i0 + r) * DD + c * 16);
        }
        CP_COMMIT(); CP_WAIT0();
    }
    __syncthreads();

    uint32_t q[4][4];
    {
        int rbase = wid * 16 + (lane & 7) + ((lane >> 3) & 1) * 8;
        #pragma unroll
        for (int kk = 0; kk < 4; kk++)
            ldsm4(q[kk], sb + STG_K(0) + toff8(rbase, 2 * kk + (lane >> 4)));
    }
    __syncthreads();

    prefetch_tile(0, sb, tid);
    prefetch_tile(1, sb, tid);

    float o[16][4];
    #pragma unroll
    for (int j = 0; j < 16; j++)
        #pragma unroll
        for (int c = 0; c < 4; c++) o[j][c] = 0.0f;
    float den0 = 0.0f, den1 = 0.0f;

    const int klr = lane & 7;
    const int kg1 = (lane >> 3) & 1;
    const int kg2 = lane >> 4;

    for (int t = 0; t < NTILES; t++) {
        uint32_t kb = sb + STG_K(t & 1);
        uint32_t vb = sb + STG_V(t & 1);
        CP_WAIT1();
        __syncthreads();

        // ---- phase 1: S = Q.K^T (fp8), exp, pack P into fp8 A-frags ----
        uint32_t pk[8][2];
        #pragma unroll
        for (int g = 0; g < 8; g++) {
            float s0[4] = {0, 0, 0, 0}, s1[4] = {0, 0, 0, 0};
            int krow = g * 16 + kg2 * 8 + klr;
            #pragma unroll
            for (int kk = 0; kk < 4; kk++) {
                uint32_t b[4];
                ldsm4(b, kb + toff8(krow, 2 * kk + kg1));
                mma_fp8(s0, q[kk], b[0], b[1]);
                mma_fp8(s1, q[kk], b[2], b[3]);
            }
            float e00 = expp(s0[0]), e01 = expp(s0[1]);
            float e02 = expp(s0[2]), e03 = expp(s0[3]);
            float e10 = expp(s1[0]), e11 = expp(s1[1]);
            float e12 = expp(s1[2]), e13 = expp(s1[3]);
            den0 += e00 + e01 + e10 + e11;
            den1 += e02 + e03 + e12 + e13;
            // row r: logical keys 4t..4t+3 = {s0[0],s0[1],s1[0],s1[1]} (K rows permuted)
            pk[g][0] = pack4e4m3(e00, e01, e10, e11);
            pk[g][1] = pack4e4m3(e02, e03, e12, e13);
        }

        // ---- phase 2: O += P.V^T (fp8), 32-key steps ----
        #pragma unroll
        for (int kk2 = 0; kk2 < 4; kk2++) {
            uint32_t a[4] = { pk[2 * kk2][0], pk[2 * kk2][1],
                              pk[2 * kk2 + 1][0], pk[2 * kk2 + 1][1] };
            #pragma unroll
            for (int dg = 0; dg < 8; dg++) {
                int drow = dg * 16 + kg2 * 8 + klr;
                uint32_t v[4];
                ldsm4(v, vb + toff8(drow, 2 * kk2 + kg1));
                mma_fp8(o[2 * dg],     a, v[0], v[1]);
                mma_fp8(o[2 * dg + 1], a, v[2], v[3]);
            }
        }

        __syncthreads();
        prefetch_tile(t + 2, sb, tid);
    }

    // ---- denominators: quad reduce (4 lanes per row) ----
    den0 += __shfl_xor_sync(0xffffffffu, den0, 1);
    den0 += __shfl_xor_sync(0xffffffffu, den0, 2);
    den1 += __shfl_xor_sync(0xffffffffu, den1, 1);
    den1 += __shfl_xor_sync(0xffffffffu, den1, 2);
    const float inv0 = 0.5f / den0;   // folds SCALE=-0.5
    const float inv1 = 0.5f / den1;

    const int r0 = wid * 16 + (lane >> 2);
    const size_t grow0 = (size_t)(i0 + r0) * DD;
    const size_t grow1 = grow0 + 8 * DD;

    float s10 = 0, s20 = 0, s11 = 0, s21 = 0;
    #pragma unroll
    for (int j = 0; j < 16; j++) {
        int col = 8 * j + (lane & 3) * 2;
        float2 xv0 = *(const float2*)(x + grow0 + col);
        float2 xv1 = *(const float2*)(x + grow1 + col);
        float y00 = fmaf(1.5f, xv0.x, -o[j][0] * inv0);
        float y01 = fmaf(1.5f, xv0.y, -o[j][1] * inv0);
        float y10 = fmaf(1.5f, xv1.x, -o[j][2] * inv1);
        float y11 = fmaf(1.5f, xv1.y, -o[j][3] * inv1);
        o[j][0] = y00; o[j][1] = y01; o[j][2] = y10; o[j][3] = y11;
        s10 += y00 + y01;           s11 += y10 + y11;
        s20 = fmaf(y00, y00, s20);  s20 = fmaf(y01, y01, s20);
        s21 = fmaf(y10, y10, s21);  s21 = fmaf(y11, y11, s21);
    }
    s10 += __shfl_xor_sync(0xffffffffu, s10, 1);
    s10 += __shfl_xor_sync(0xffffffffu, s10, 2);
    s20 += __shfl_xor_sync(0xffffffffu, s20, 1);
    s20 += __shfl_xor_sync(0xffffffffu, s20, 2);
    s11 += __shfl_xor_sync(0xffffffffu, s11, 1);
    s11 += __shfl_xor_sync(0xffffffffu, s11, 2);
    s21 += __shfl_xor_sync(0xffffffffu, s21, 1);
    s21 += __shfl_xor_sync(0xffffffffu, s21, 2);

    const float mu0 = s10 * (1.0f / DD);
    const float mu1 = s11 * (1.0f / DD);
    const float rs0 = rsqrtf(s20 * (1.0f / DD) - mu0 * mu0 + 1e-5f);
    const float rs1 = rsqrtf(s21 * (1.0f / DD) - mu1 * mu1 + 1e-5f);

    #pragma unroll
    for (int j = 0; j < 16; j++) {
        int col = 8 * j + (lane & 3) * 2;
        float2 gm = *(const float2*)(gamma + col);
        float2 bt = *(const float2*)(beta + col);
        float2 o0, o1;
        o0.x = fmaf((o[j][0] - mu0) * rs0, gm.x, bt.x);
        o0.y = fmaf((o[j][1] - mu0) * rs0, gm.y, bt.y);
        o1.x = fmaf((o[j][2] - mu1) * rs1, gm.x, bt.x);
        o1.y = fmaf((o[j][3] - mu1) * rs1, gm.y, bt.y);
        *(float2*)(out + grow0 + col) = o0;
        *(float2*)(out + grow1 + col) = o1;
    }
}

// ---------------------------------------------------------------------------
extern "C" void kernel_launch(void* const* d_in, const int* in_sizes, int n_in,
                              void* d_out, int out_size) {
    const float* x     = (const float*)d_in[0];
    const float* gamma = (const float*)d_in[1];
    const float* beta  = (const float*)d_in[2];
    float* out = (float*)d_out;

    prep_kernel<<<NROWS / 8, 256>>>(x);
    trans_kernel<<<NROWS / 128, 256>>>(x);

    cudaFuncSetAttribute(attn_kernel,
                         cudaFuncAttributeMaxDynamicSharedMemorySize, SMEM_BYTES);
    attn_kernel<<<NROWS / BM, NTHREADS, SMEM_BYTES>>>(x, gamma, beta, out);
}

// round 11
// speedup vs baseline: 1.1314x; 1.1314x over previous
#include <cuda_runtime.h>
#include <cuda_bf16.h>
#include <cstdint>

#define NROWS 16384
#define DD    128
#define BM    64
#define BN    128
#define KSPLIT 2
#define TILES_PER (NROWS / BN / KSPLIT)   // 64
#define NTHREADS 128

// device globals (allocation-free rule)
__device__ __nv_bfloat16 g_nx[NROWS * DD];            // normalized rows (K == V base)
__device__ float         g_norm[NROWS];               // row norms
__device__ float         g_opart[KSPLIT][NROWS][DD];  // split-K O partials (16 MB)
__device__ float         g_dpart[KSPLIT][NROWS];      // split-K den partials

// ---------------------------------------------------------------------------
__device__ __forceinline__ uint32_t smem_u32(const void* p) {
    uint32_t a;
    asm("{ .reg .u64 t; cvta.to.shared.u64 t, %1; cvt.u32.u64 %0, t; }"
        : "=r"(a) : "l"(p));
    return a;
}
__device__ __forceinline__ void cpa16(uint32_t dst, const void* src) {
    asm volatile("cp.async.cg.shared.global [%0], [%1], 16;"
                 :: "r"(dst), "l"(src) : "memory");
}
#define CP_COMMIT() asm volatile("cp.async.commit_group;" ::: "memory")
#define CP_WAIT1()  asm volatile("cp.async.wait_group 1;" ::: "memory")
#define CP_WAIT0()  asm volatile("cp.async.wait_group 0;" ::: "memory")

__device__ __forceinline__ void ldsm4(uint32_t* r, uint32_t addr) {
    asm volatile("ldmatrix.sync.aligned.m8n8.x4.shared.b16 {%0,%1,%2,%3}, [%4];"
        : "=r"(r[0]), "=r"(r[1]), "=r"(r[2]), "=r"(r[3]) : "r"(addr));
}
__device__ __forceinline__ void ldsm4t(uint32_t* r, uint32_t addr) {
    asm volatile("ldmatrix.sync.aligned.m8n8.x4.trans.shared.b16 {%0,%1,%2,%3}, [%4];"
        : "=r"(r[0]), "=r"(r[1]), "=r"(r[2]), "=r"(r[3]) : "r"(addr));
}
__device__ __forceinline__ void mma16816(float* c, const uint32_t* a,
                                         uint32_t b0, uint32_t b1) {
    asm volatile("mma.sync.aligned.m16n8k16.row.col.f32.bf16.bf16.f32 "
        "{%0,%1,%2,%3}, {%4,%5,%6,%7}, {%8,%9}, {%0,%1,%2,%3};"
        : "+f"(c[0]), "+f"(c[1]), "+f"(c[2]), "+f"(c[3])
        : "r"(a[0]), "r"(a[1]), "r"(a[2]), "r"(a[3]), "r"(b0), "r"(b1));
}
__device__ __forceinline__ uint32_t packbf(float lo, float hi) {
    uint32_t d;
    asm("cvt.rn.bf16x2.f32 %0, %1, %2;" : "=r"(d) : "f"(hi), "f"(lo));
    return d;
}
// Degree-7 Taylor exp, s in [-1,1]: rel err < 3e-5, pure FFMA
__device__ __forceinline__ float expp(float s) {
    float p = 1.9841270e-4f;
    p = fmaf(p, s, 1.3888889e-3f);
    p = fmaf(p, s, 8.3333333e-3f);
    p = fmaf(p, s, 4.1666667e-2f);
    p = fmaf(p, s, 1.6666667e-1f);
    p = fmaf(p, s, 0.5f);
    p = fmaf(p, s, 1.0f);
    p = fmaf(p, s, 1.0f);
    return p;
}
// Tile smem layout: row r (0..127) * 256B, 16B chunk c swizzled by row
__device__ __forceinline__ uint32_t toff(int r, int c) {
    return (uint32_t)(r * 256 + ((c ^ (r & 7)) << 4));
}

#define STG_NX(s) ((s) * 32768)
#define STG_KN(s) (65536 + (s) * 512)
#define SMEM_BYTES (65536 + 1024)

// ---------------------------------------------------------------------------
__global__ void prep_kernel(const float* __restrict__ x) {
    int row  = blockIdx.x * 8 + (threadIdx.x >> 5);
    int lane = threadIdx.x & 31;
    float4 v = *(const float4*)(x + (size_t)row * DD + lane * 4);
    float ss = v.x * v.x + v.y * v.y + v.z * v.z + v.w * v.w;
    #pragma unroll
    for (int o = 16; o; o >>= 1) ss += __shfl_xor_sync(0xffffffffu, ss, o);
    float nrm = sqrtf(ss);
    float inv = 1.0f / fmaxf(nrm, 1e-12f);
    size_t base = (size_t)row * DD + lane * 4;
    *(__nv_bfloat162*)(g_nx + base)     = __floats2bfloat162_rn(v.x * inv, v.y * inv);
    *(__nv_bfloat162*)(g_nx + base + 2) = __floats2bfloat162_rn(v.z * inv, v.w * inv);
    if (lane == 0) g_norm[row] = nrm;
}

// ---------------------------------------------------------------------------
__device__ __forceinline__ void prefetch_tile(int tt, int tend, uint32_t sb, int tid) {
    if (tt < tend) {
        uint32_t nb = sb + STG_NX(tt & 1);
        int j0 = tt * BN;
        #pragma unroll
        for (int i = 0; i < 16; i++) {
            int idx = tid + i * NTHREADS;
            int r = idx >> 4, c = idx & 15;
            cpa16(nb + toff(r, c), g_nx + (size_t)(j0 + r) * DD + c * 8);
        }
        if (tid < 32)
            cpa16(sb + STG_KN(tt & 1) + tid * 16, g_norm + j0 + tid * 4);
    }
    CP_COMMIT();
}

// ---------------------------------------------------------------------------
// Split-K attention partial. BM=64, 4 warps, 3 CTAs/SM (regs <= 170).
// V tile == K tile (nx); key norm folded into packed P. Round-7 body.
// ---------------------------------------------------------------------------
__global__ __launch_bounds__(NTHREADS, 3)
void attn_kernel() {
    extern __shared__ char smem[];
    uint32_t sb = smem_u32(smem);
    const int tid  = threadIdx.x;
    const int wid  = tid >> 5;
    const int lane = tid & 31;
    const int qt   = blockIdx.x >> 1;
    const int half = blockIdx.x & 1;
    const int i0   = qt * BM;
    const int t0   = half * TILES_PER;
    const int tend = t0 + TILES_PER;

    // ---- stage Q tile (64 rows) into stage0 area, load Q fragments ----
    {
        uint32_t qb = sb + STG_NX(t0 & 1);
        #pragma unroll
        for (int i = 0; i < 8; i++) {
            int idx = tid + i * NTHREADS;
            int r = idx >> 4, c = idx & 15;
            cpa16(qb + toff(r, c), g_nx + (size_t)(i0 + r) * DD + c * 8);
        }
        CP_COMMIT(); CP_WAIT0();
    }
    __syncthreads();

    uint32_t q[8][4];
    {
        int rbase = wid * 16 + (lane & 7) + ((lane >> 3) & 1) * 8;
        #pragma unroll
        for (int kk = 0; kk < 8; kk++)
            ldsm4(q[kk], sb + STG_NX(t0 & 1) + toff(rbase, 2 * kk + (lane >> 4)));
    }
    __syncthreads();

    prefetch_tile(t0, tend, sb, tid);
    prefetch_tile(t0 + 1, tend, sb, tid);

    float o[16][4];
    #pragma unroll
    for (int j = 0; j < 16; j++)
        #pragma unroll
        for (int c = 0; c < 4; c++) o[j][c] = 0.0f;
    float den0 = 0.0f, den1 = 0.0f;

    const int klr = lane & 7;
    const int kg1 = (lane >> 3) & 1;
    const int kg2 = lane >> 4;
    const int jq  = 2 * (lane & 3);

    for (int t = t0; t < tend; t++) {
        uint32_t nb  = sb + STG_NX(t & 1);
        uint32_t knb = sb + STG_KN(t & 1);
        CP_WAIT1();
        __syncthreads();

        // ---- phase 1: S = Q.K^T, exp, fold key norm, pack ----
        uint32_t pk[32];
        #pragma unroll
        for (int g = 0; g < 8; g++) {
            float s0[4] = {0, 0, 0, 0}, s1[4] = {0, 0, 0, 0};
            int krow = g * 16 + kg2 * 8 + klr;
            #pragma unroll
            for (int kk = 0; kk < 8; kk++) {
                uint32_t b[4];
                ldsm4(b, nb + toff(krow, 2 * kk + kg1));
                mma16816(s0, q[kk], b[0], b[1]);
                mma16816(s1, q[kk], b[2], b[3]);
            }
            float e00 = expp(s0[0]), e01 = expp(s0[1]);
            float e02 = expp(s0[2]), e03 = expp(s0[3]);
            float e10 = expp(s1[0]), e11 = expp(s1[1]);
            float e12 = expp(s1[2]), e13 = expp(s1[3]);
            den0 += e00 + e01 + e10 + e11;
            den1 += e02 + e03 + e12 + e13;
            float2 kn01, kn89;
            asm("ld.shared.v2.f32 {%0,%1}, [%2];" : "=f"(kn01.x), "=f"(kn01.y)
                : "r"(knb + (g * 16 + jq) * 4));
            asm("ld.shared.v2.f32 {%0,%1}, [%2];" : "=f"(kn89.x), "=f"(kn89.y)
                : "r"(knb + (g * 16 + 8 + jq) * 4));
            pk[4 * g + 0] = packbf(e00 * kn01.x, e01 * kn01.y);
            pk[4 * g + 1] = packbf(e02 * kn01.x, e03 * kn01.y);
            pk[4 * g + 2] = packbf(e10 * kn89.x, e11 * kn89.y);
            pk[4 * g + 3] = packbf(e12 * kn89.x, e13 * kn89.y);
        }

        // ---- phase 2: O += P . NX (trans loads on the SAME nx tile) ----
        #pragma unroll
        for (int kk = 0; kk < 8; kk++) {
            int vrow = kk * 16 + kg1 * 8 + klr;
            #pragma unroll
            for (int dg = 0; dg < 8; dg++) {
                uint32_t v[4];
                ldsm4t(v, nb + toff(vrow, 2 * dg + kg2));
                mma16816(o[2 * dg],     &pk[4 * kk], v[0], v[1]);
                mma16816(o[2 * dg + 1], &pk[4 * kk], v[2], v[3]);
            }
        }

        __syncthreads();
        prefetch_tile(t + 2, tend, sb, tid);
    }

    // ---- write partials: den (quad-reduced) + O frags ----
    den0 += __shfl_xor_sync(0xffffffffu, den0, 1);
    den0 += __shfl_xor_sync(0xffffffffu, den0, 2);
    den1 += __shfl_xor_sync(0xffffffffu, den1, 1);
    den1 += __shfl_xor_sync(0xffffffffu, den1, 2);

    const int ra = i0 + wid * 16 + (lane >> 2);
    if ((lane & 3) == 0) {
        g_dpart[half][ra]     = den0;
        g_dpart[half][ra + 8] = den1;
    }
    #pragma unroll
    for (int j = 0; j < 16; j++) {
        int col = 8 * j + jq;
        *(float2*)&g_opart[half][ra][col]     = make_float2(o[j][0], o[j][1]);
        *(float2*)&g_opart[half][ra + 8][col] = make_float2(o[j][2], o[j][3]);
    }
}

// ---------------------------------------------------------------------------
// Epilogue: combine split-K partials, y = 1.5x - 0.5*O/den, LayerNorm.
// ---------------------------------------------------------------------------
__global__ __launch_bounds__(256)
void ln_kernel(const float* __restrict__ x,
               const float* __restrict__ gamma,
               const float* __restrict__ beta,
               float* __restrict__ out) {
    const int row  = blockIdx.x * 8 + (threadIdx.x >> 5);
    const int lane = threadIdx.x & 31;
    const int c    = lane * 4;

    float4 o0 = *(const float4*)&g_opart[0][row][c];
    float4 o1 = *(const float4*)&g_opart[1][row][c];
    const float den = g_dpart[0][row] + g_dpart[1][row];
    const float inv = 0.5f / den;   // folds SCALE=-0.5
    float4 xv = *(const float4*)(x + (size_t)row * DD + c);

    float y0 = fmaf(1.5f, xv.x, -(o0.x + o1.x) * inv);
    float y1 = fmaf(1.5f, xv.y, -(o0.y + o1.y) * inv);
    float y2 = fmaf(1.5f, xv.z, -(o0.z + o1.z) * inv);
    float y3 = fmaf(1.5f, xv.w, -(o0.w + o1.w) * inv);

    float s1 = y0 + y1 + y2 + y3;
    float s2 = fmaf(y0, y0, fmaf(y1, y1, fmaf(y2, y2, y3 * y3)));
    #pragma unroll
    for (int o = 16; o; o >>= 1) {
        s1 += __shfl_xor_sync(0xffffffffu, s1, o);
        s2 += __shfl_xor_sync(0xffffffffu, s2, o);
    }
    const float mu   = s1 * (1.0f / DD);
    const float var  = s2 * (1.0f / DD) - mu * mu;
    const float rstd = rsqrtf(var + 1e-5f);

    float4 gm = *(const float4*)(gamma + c);
    float4 bt = *(const float4*)(beta + c);
    float4 r;
    r.x = fmaf((y0 - mu) * rstd, gm.x, bt.x);
    r.y = fmaf((y1 - mu) * rstd, gm.y, bt.y);
    r.z = fmaf((y2 - mu) * rstd, gm.z, bt.z);
    r.w = fmaf((y3 - mu) * rstd, gm.w, bt.w);
    *(float4*)(out + (size_t)row * DD + c) = r;
}

// ---------------------------------------------------------------------------
extern "C" void kernel_launch(void* const* d_in, const int* in_sizes, int n_in,
                              void* d_out, int out_size) {
    const float* x     = (const float*)d_in[0];
    const float* gamma = (const float*)d_in[1];
    const float* beta  = (const float*)d_in[2];
    float* out = (float*)d_out;

    prep_kernel<<<NROWS / 8, 256>>>(x);

    cudaFuncSetAttribute(attn_kernel,
                         cudaFuncAttributeMaxDynamicSharedMemorySize, SMEM_BYTES);
    attn_kernel<<<(NROWS / BM) * KSPLIT, NTHREADS, SMEM_BYTES>>>();

    ln_kernel<<<NROWS / 8, 256>>>(x, gamma, beta, out);
}

// round 12
// speedup vs baseline: 1.3601x; 1.2021x over previous
#include <cuda_runtime.h>
#include <cuda_bf16.h>
#include <cstdint>

#define NROWS 16384
#define DD    128
#define BM    64
#define BN    128
#define KSPLIT 4
#define TILES_PER (NROWS / BN / KSPLIT)   // 32
#define NTHREADS 128

// device globals (allocation-free rule)
__device__ __nv_bfloat16 g_nx[NROWS * DD];            // normalized rows (K == V base)
__device__ float         g_norm[NROWS];               // row norms
__device__ float         g_opart[KSPLIT][NROWS][DD];  // split-K O partials (32 MB)
__device__ float         g_dpart[KSPLIT][NROWS];      // split-K den partials

// ---------------------------------------------------------------------------
__device__ __forceinline__ uint32_t smem_u32(const void* p) {
    uint32_t a;
    asm("{ .reg .u64 t; cvta.to.shared.u64 t, %1; cvt.u32.u64 %0, t; }"
        : "=r"(a) : "l"(p));
    return a;
}
__device__ __forceinline__ void cpa16(uint32_t dst, const void* src) {
    asm volatile("cp.async.cg.shared.global [%0], [%1], 16;"
                 :: "r"(dst), "l"(src) : "memory");
}
#define CP_COMMIT() asm volatile("cp.async.commit_group;" ::: "memory")
#define CP_WAIT1()  asm volatile("cp.async.wait_group 1;" ::: "memory")
#define CP_WAIT0()  asm volatile("cp.async.wait_group 0;" ::: "memory")

__device__ __forceinline__ void ldsm4(uint32_t* r, uint32_t addr) {
    asm volatile("ldmatrix.sync.aligned.m8n8.x4.shared.b16 {%0,%1,%2,%3}, [%4];"
        : "=r"(r[0]), "=r"(r[1]), "=r"(r[2]), "=r"(r[3]) : "r"(addr));
}
__device__ __forceinline__ void ldsm4t(uint32_t* r, uint32_t addr) {
    asm volatile("ldmatrix.sync.aligned.m8n8.x4.trans.shared.b16 {%0,%1,%2,%3}, [%4];"
        : "=r"(r[0]), "=r"(r[1]), "=r"(r[2]), "=r"(r[3]) : "r"(addr));
}
__device__ __forceinline__ void mma16816(float* c, const uint32_t* a,
                                         uint32_t b0, uint32_t b1) {
    asm volatile("mma.sync.aligned.m16n8k16.row.col.f32.bf16.bf16.f32 "
        "{%0,%1,%2,%3}, {%4,%5,%6,%7}, {%8,%9}, {%0,%1,%2,%3};"
        : "+f"(c[0]), "+f"(c[1]), "+f"(c[2]), "+f"(c[3])
        : "r"(a[0]), "r"(a[1]), "r"(a[2]), "r"(a[3]), "r"(b0), "r"(b1));
}
__device__ __forceinline__ uint32_t packbf(float lo, float hi) {
    uint32_t d;
    asm("cvt.rn.bf16x2.f32 %0, %1, %2;" : "=r"(d) : "f"(hi), "f"(lo));
    return d;
}
// Degree-7 Taylor exp, s in [-1,1]: rel err < 3e-5, pure FFMA
__device__ __forceinline__ float expp(float s) {
    float p = 1.9841270e-4f;
    p = fmaf(p, s, 1.3888889e-3f);
    p = fmaf(p, s, 8.3333333e-3f);
    p = fmaf(p, s, 4.1666667e-2f);
    p = fmaf(p, s, 1.6666667e-1f);
    p = fmaf(p, s, 0.5f);
    p = fmaf(p, s, 1.0f);
    p = fmaf(p, s, 1.0f);
    return p;
}
// Tile smem layout: row r (0..127) * 256B, 16B chunk c swizzled by row
__device__ __forceinline__ uint32_t toff(int r, int c) {
    return (uint32_t)(r * 256 + ((c ^ (r & 7)) << 4));
}

#define STG_NX(s) ((s) * 32768)
#define STG_KN(s) (65536 + (s) * 512)
#define SMEM_BYTES (65536 + 1024)

// ---------------------------------------------------------------------------
__global__ void prep_kernel(const float* __restrict__ x) {
    int row  = blockIdx.x * 8 + (threadIdx.x >> 5);
    int lane = threadIdx.x & 31;
    float4 v = *(const float4*)(x + (size_t)row * DD + lane * 4);
    float ss = v.x * v.x + v.y * v.y + v.z * v.z + v.w * v.w;
    #pragma unroll
    for (int o = 16; o; o >>= 1) ss += __shfl_xor_sync(0xffffffffu, ss, o);
    float nrm = sqrtf(ss);
    float inv = 1.0f / fmaxf(nrm, 1e-12f);
    size_t base = (size_t)row * DD + lane * 4;
    *(__nv_bfloat162*)(g_nx + base)     = __floats2bfloat162_rn(v.x * inv, v.y * inv);
    *(__nv_bfloat162*)(g_nx + base + 2) = __floats2bfloat162_rn(v.z * inv, v.w * inv);
    if (lane == 0) g_norm[row] = nrm;
}

// ---------------------------------------------------------------------------
__device__ __forceinline__ void prefetch_tile(int tt, int tend, uint32_t sb, int tid) {
    if (tt < tend) {
        uint32_t nb = sb + STG_NX(tt & 1);
        int j0 = tt * BN;
        #pragma unroll
        for (int i = 0; i < 16; i++) {
            int idx = tid + i * NTHREADS;
            int r = idx >> 4, c = idx & 15;
            cpa16(nb + toff(r, c), g_nx + (size_t)(j0 + r) * DD + c * 8);
        }
        if (tid < 32)
            cpa16(sb + STG_KN(tt & 1) + tid * 16, g_norm + j0 + tid * 4);
    }
    CP_COMMIT();
}

// ---------------------------------------------------------------------------
// Split-K attention partial. BM=64, 4 warps, 3 CTAs/SM, fused per-group body
// (pk[4] only -> ~140 regs, no spills at the 170-reg cap).
// ---------------------------------------------------------------------------
__global__ __launch_bounds__(NTHREADS, 3)
void attn_kernel() {
    extern __shared__ char smem[];
    uint32_t sb = smem_u32(smem);
    const int tid  = threadIdx.x;
    const int wid  = tid >> 5;
    const int lane = tid & 31;
    const int qt   = blockIdx.x >> 2;
    const int half = blockIdx.x & 3;
    const int i0   = qt * BM;
    const int t0   = half * TILES_PER;
    const int tend = t0 + TILES_PER;

    // ---- stage Q tile (64 rows) into stage-(t0&1) area, load Q fragments ----
    {
        uint32_t qb = sb + STG_NX(t0 & 1);
        #pragma unroll
        for (int i = 0; i < 8; i++) {
            int idx = tid + i * NTHREADS;
            int r = idx >> 4, c = idx & 15;
            cpa16(qb + toff(r, c), g_nx + (size_t)(i0 + r) * DD + c * 8);
        }
        CP_COMMIT(); CP_WAIT0();
    }
    __syncthreads();

    uint32_t q[8][4];
    {
        int rbase = wid * 16 + (lane & 7) + ((lane >> 3) & 1) * 8;
        #pragma unroll
        for (int kk = 0; kk < 8; kk++)
            ldsm4(q[kk], sb + STG_NX(t0 & 1) + toff(rbase, 2 * kk + (lane >> 4)));
    }
    __syncthreads();

    prefetch_tile(t0, tend, sb, tid);
    prefetch_tile(t0 + 1, tend, sb, tid);

    float o[16][4];
    #pragma unroll
    for (int j = 0; j < 16; j++)
        #pragma unroll
        for (int c = 0; c < 4; c++) o[j][c] = 0.0f;
    float den0 = 0.0f, den1 = 0.0f;

    const int klr = lane & 7;
    const int kg1 = (lane >> 3) & 1;
    const int kg2 = lane >> 4;
    const int jq  = 2 * (lane & 3);

    for (int t = t0; t < tend; t++) {
        uint32_t nb  = sb + STG_NX(t & 1);
        uint32_t knb = sb + STG_KN(t & 1);
        CP_WAIT1();
        __syncthreads();

        // ---- fused per-16-key-group pipeline: S -> exp -> O (pk[4] live) ----
        #pragma unroll
        for (int g = 0; g < 8; g++) {
            float s0[4] = {0, 0, 0, 0}, s1[4] = {0, 0, 0, 0};
            int krow = g * 16 + kg2 * 8 + klr;
            #pragma unroll
            for (int kk = 0; kk < 8; kk++) {
                uint32_t b[4];
                ldsm4(b, nb + toff(krow, 2 * kk + kg1));
                mma16816(s0, q[kk], b[0], b[1]);
                mma16816(s1, q[kk], b[2], b[3]);
            }
            float e00 = expp(s0[0]), e01 = expp(s0[1]);
            float e02 = expp(s0[2]), e03 = expp(s0[3]);
            float e10 = expp(s1[0]), e11 = expp(s1[1]);
            float e12 = expp(s1[2]), e13 = expp(s1[3]);
            den0 += e00 + e01 + e10 + e11;
            den1 += e02 + e03 + e12 + e13;
            float2 kn01, kn89;
            asm("ld.shared.v2.f32 {%0,%1}, [%2];" : "=f"(kn01.x), "=f"(kn01.y)
                : "r"(knb + (g * 16 + jq) * 4));
            asm("ld.shared.v2.f32 {%0,%1}, [%2];" : "=f"(kn89.x), "=f"(kn89.y)
                : "r"(knb + (g * 16 + 8 + jq) * 4));
            uint32_t pk[4];
            pk[0] = packbf(e00 * kn01.x, e01 * kn01.y);
            pk[1] = packbf(e02 * kn01.x, e03 * kn01.y);
            pk[2] = packbf(e10 * kn89.x, e11 * kn89.y);
            pk[3] = packbf(e12 * kn89.x, e13 * kn89.y);
            // O += P[:,g] . NX[g,:] (trans loads on the SAME nx tile)
            int vrow = g * 16 + kg1 * 8 + klr;
            #pragma unroll
            for (int dg = 0; dg < 8; dg++) {
                uint32_t v[4];
                ldsm4t(v, nb + toff(vrow, 2 * dg + kg2));
                mma16816(o[2 * dg],     pk, v[0], v[1]);
                mma16816(o[2 * dg + 1], pk, v[2], v[3]);
            }
        }

        __syncthreads();
        prefetch_tile(t + 2, tend, sb, tid);
    }

    // ---- write partials: den (quad-reduced) + O frags ----
    den0 += __shfl_xor_sync(0xffffffffu, den0, 1);
    den0 += __shfl_xor_sync(0xffffffffu, den0, 2);
    den1 += __shfl_xor_sync(0xffffffffu, den1, 1);
    den1 += __shfl_xor_sync(0xffffffffu, den1, 2);

    const int ra = i0 + wid * 16 + (lane >> 2);
    if ((lane & 3) == 0) {
        g_dpart[half][ra]     = den0;
        g_dpart[half][ra + 8] = den1;
    }
    #pragma unroll
    for (int j = 0; j < 16; j++) {
        int col = 8 * j + jq;
        *(float2*)&g_opart[half][ra][col]     = make_float2(o[j][0], o[j][1]);
        *(float2*)&g_opart[half][ra + 8][col] = make_float2(o[j][2], o[j][3]);
    }
}

// ---------------------------------------------------------------------------
// Epilogue: combine KSPLIT partials, y = 1.5x - 0.5*O/den, LayerNorm.
// ---------------------------------------------------------------------------
__global__ __launch_bounds__(256)
void ln_kernel(const float* __restrict__ x,
               const float* __restrict__ gamma,
               const float* __restrict__ beta,
               float* __restrict__ out) {
    const int row  = blockIdx.x * 8 + (threadIdx.x >> 5);
    const int lane = threadIdx.x & 31;
    const int c    = lane * 4;

    float4 oa = *(const float4*)&g_opart[0][row][c];
    float den = g_dpart[0][row];
    #pragma unroll
    for (int h = 1; h < KSPLIT; h++) {
        float4 ob = *(const float4*)&g_opart[h][row][c];
        oa.x += ob.x; oa.y += ob.y; oa.z += ob.z; oa.w += ob.w;
        den += g_dpart[h][row];
    }
    const float inv = 0.5f / den;   // folds SCALE=-0.5
    float4 xv = *(const float4*)(x + (size_t)row * DD + c);

    float y0 = fmaf(1.5f, xv.x, -oa.x * inv);
    float y1 = fmaf(1.5f, xv.y, -oa.y * inv);
    float y2 = fmaf(1.5f, xv.z, -oa.z * inv);
    float y3 = fmaf(1.5f, xv.w, -oa.w * inv);

    float s1 = y0 + y1 + y2 + y3;
    float s2 = fmaf(y0, y0, fmaf(y1, y1, fmaf(y2, y2, y3 * y3)));
    #pragma unroll
    for (int o = 16; o; o >>= 1) {
        s1 += __shfl_xor_sync(0xffffffffu, s1, o);
        s2 += __shfl_xor_sync(0xffffffffu, s2, o);
    }
    const float mu   = s1 * (1.0f / DD);
    const float var  = s2 * (1.0f / DD) - mu * mu;
    const float rstd = rsqrtf(var + 1e-5f);

    float4 gm = *(const float4*)(gamma + c);
    float4 bt = *(const float4*)(beta + c);
    float4 r;
    r.x = fmaf((y0 - mu) * rstd, gm.x, bt.x);
    r.y = fmaf((y1 - mu) * rstd, gm.y, bt.y);
    r.z = fmaf((y2 - mu) * rstd, gm.z, bt.z);
    r.w = fmaf((y3 - mu) * rstd, gm.w, bt.w);
    *(float4*)(out + (size_t)row * DD + c) = r;
}

// ---------------------------------------------------------------------------
extern "C" void kernel_launch(void* const* d_in, const int* in_sizes, int n_in,
                              void* d_out, int out_size) {
    const float* x     = (const float*)d_in[0];
    const float* gamma = (const float*)d_in[1];
    const float* beta  = (const float*)d_in[2];
    float* out = (float*)d_out;

    prep_kernel<<<NROWS / 8, 256>>>(x);

    cudaFuncSetAttribute(attn_kernel,
                         cudaFuncAttributeMaxDynamicSharedMemorySize, SMEM_BYTES);
    attn_kernel<<<(NROWS / BM) * KSPLIT, NTHREADS, SMEM_BYTES>>>();

    ln_kernel<<<NROWS / 8, 256>>>(x, gamma, beta, out);
}

// round 13
// speedup vs baseline: 1.4069x; 1.0344x over previous
#include <cuda_runtime.h>
#include <cuda_bf16.h>
#include <cstdint>

#define NROWS 16384
#define DD    128
#define BM    64
#define BN    128
#define KSPLIT 2
#define TILES_PER (NROWS / BN / KSPLIT)   // 64
#define NTHREADS 128

// device globals (allocation-free rule)
__device__ __nv_bfloat16 g_nx[NROWS * DD];            // normalized rows (K == V base)
__device__ float         g_norm[NROWS];               // row norms
__device__ float         g_opart[KSPLIT][NROWS][DD];  // split-K O partials
__device__ float         g_dpart[KSPLIT][NROWS];      // split-K den partials

// ---------------------------------------------------------------------------
__device__ __forceinline__ uint32_t smem_u32(const void* p) {
    uint32_t a;
    asm("{ .reg .u64 t; cvta.to.shared.u64 t, %1; cvt.u32.u64 %0, t; }"
        : "=r"(a) : "l"(p));
    return a;
}
__device__ __forceinline__ void cpa16(uint32_t dst, const void* src) {
    asm volatile("cp.async.cg.shared.global [%0], [%1], 16;"
                 :: "r"(dst), "l"(src) : "memory");
}
#define CP_COMMIT() asm volatile("cp.async.commit_group;" ::: "memory")
#define CP_WAIT1()  asm volatile("cp.async.wait_group 1;" ::: "memory")
#define CP_WAIT0()  asm volatile("cp.async.wait_group 0;" ::: "memory")

__device__ __forceinline__ void ldsm4(uint32_t* r, uint32_t addr) {
    asm volatile("ldmatrix.sync.aligned.m8n8.x4.shared.b16 {%0,%1,%2,%3}, [%4];"
        : "=r"(r[0]), "=r"(r[1]), "=r"(r[2]), "=r"(r[3]) : "r"(addr));
}
__device__ __forceinline__ void ldsm4t(uint32_t* r, uint32_t addr) {
    asm volatile("ldmatrix.sync.aligned.m8n8.x4.trans.shared.b16 {%0,%1,%2,%3}, [%4];"
        : "=r"(r[0]), "=r"(r[1]), "=r"(r[2]), "=r"(r[3]) : "r"(addr));
}
__device__ __forceinline__ void mma16816(float* c, const uint32_t* a,
                                         uint32_t b0, uint32_t b1) {
    asm volatile("mma.sync.aligned.m16n8k16.row.col.f32.bf16.bf16.f32 "
        "{%0,%1,%2,%3}, {%4,%5,%6,%7}, {%8,%9}, {%0,%1,%2,%3};"
        : "+f"(c[0]), "+f"(c[1]), "+f"(c[2]), "+f"(c[3])
        : "r"(a[0]), "r"(a[1]), "r"(a[2]), "r"(a[3]), "r"(b0), "r"(b1));
}
__device__ __forceinline__ uint32_t packbf(float lo, float hi) {
    uint32_t d;
    asm("cvt.rn.bf16x2.f32 %0, %1, %2;" : "=r"(d) : "f"(hi), "f"(lo));
    return d;
}
// Degree-7 Taylor exp, s in [-1,1]: rel err < 3e-5, pure FFMA
__device__ __forceinline__ float expp(float s) {
    float p = 1.9841270e-4f;
    p = fmaf(p, s, 1.3888889e-3f);
    p = fmaf(p, s, 8.3333333e-3f);
    p = fmaf(p, s, 4.1666667e-2f);
    p = fmaf(p, s, 1.6666667e-1f);
    p = fmaf(p, s, 0.5f);
    p = fmaf(p, s, 1.0f);
    p = fmaf(p, s, 1.0f);
    return p;
}
// Tile smem layout: row r (0..127) * 256B, 16B chunk c swizzled by row
__device__ __forceinline__ uint32_t toff(int r, int c) {
    return (uint32_t)(r * 256 + ((c ^ (r & 7)) << 4));
}

#define STG_NX(s) ((s) * 32768)
#define STG_KN(s) (65536 + (s) * 512)
#define SMEM_BYTES (65536 + 1024)

// ---------------------------------------------------------------------------
__global__ void prep_kernel(const float* __restrict__ x) {
    int row  = blockIdx.x * 8 + (threadIdx.x >> 5);
    int lane = threadIdx.x & 31;
    float4 v = *(const float4*)(x + (size_t)row * DD + lane * 4);
    float ss = v.x * v.x + v.y * v.y + v.z * v.z + v.w * v.w;
    #pragma unroll
    for (int o = 16; o; o >>= 1) ss += __shfl_xor_sync(0xffffffffu, ss, o);
    float nrm = sqrtf(ss);
    float inv = 1.0f / fmaxf(nrm, 1e-12f);
    size_t base = (size_t)row * DD + lane * 4;
    *(__nv_bfloat162*)(g_nx + base)     = __floats2bfloat162_rn(v.x * inv, v.y * inv);
    *(__nv_bfloat162*)(g_nx + base + 2) = __floats2bfloat162_rn(v.z * inv, v.w * inv);
    if (lane == 0) g_norm[row] = nrm;
}

// ---------------------------------------------------------------------------
__device__ __forceinline__ void prefetch_tile(int tt, int tend, uint32_t sb, int tid) {
    if (tt < tend) {
        uint32_t nb = sb + STG_NX(tt & 1);
        int j0 = tt * BN;
        #pragma unroll
        for (int i = 0; i < 16; i++) {
            int idx = tid + i * NTHREADS;
            int r = idx >> 4, c = idx & 15;
            cpa16(nb + toff(r, c), g_nx + (size_t)(j0 + r) * DD + c * 8);
        }
        if (tid < 32)
            cpa16(sb + STG_KN(tt & 1) + tid * 16, g_norm + j0 + tid * 4);
    }
    CP_COMMIT();
}

// ---------------------------------------------------------------------------
// Split-K attention partial. Round-7 body verbatim: BM=64, 4 warps,
// 2 CTAs/SM, phase-separated S->exp->O. Only the launch shape changed.
// ---------------------------------------------------------------------------
__global__ __launch_bounds__(NTHREADS, 2)
void attn_kernel() {
    extern __shared__ char smem[];
    uint32_t sb = smem_u32(smem);
    const int tid  = threadIdx.x;
    const int wid  = tid >> 5;
    const int lane = tid & 31;
    const int qt   = blockIdx.x >> 1;
    const int half = blockIdx.x & 1;
    const int i0   = qt * BM;
    const int t0   = half * TILES_PER;
    const int tend = t0 + TILES_PER;

    // ---- stage Q tile (64 rows) into stage-(t0&1) area, load Q fragments ----
    {
        uint32_t qb = sb + STG_NX(t0 & 1);
        #pragma unroll
        for (int i = 0; i < 8; i++) {
            int idx = tid + i * NTHREADS;
            int r = idx >> 4, c = idx & 15;
            cpa16(qb + toff(r, c), g_nx + (size_t)(i0 + r) * DD + c * 8);
        }
        CP_COMMIT(); CP_WAIT0();
    }
    __syncthreads();

    uint32_t q[8][4];
    {
        int rbase = wid * 16 + (lane & 7) + ((lane >> 3) & 1) * 8;
        #pragma unroll
        for (int kk = 0; kk < 8; kk++)
            ldsm4(q[kk], sb + STG_NX(t0 & 1) + toff(rbase, 2 * kk + (lane >> 4)));
    }
    __syncthreads();

    prefetch_tile(t0, tend, sb, tid);
    prefetch_tile(t0 + 1, tend, sb, tid);

    float o[16][4];
    #pragma unroll
    for (int j = 0; j < 16; j++)
        #pragma unroll
        for (int c = 0; c < 4; c++) o[j][c] = 0.0f;
    float den0 = 0.0f, den1 = 0.0f;

    const int klr = lane & 7;
    const int kg1 = (lane >> 3) & 1;
    const int kg2 = lane >> 4;
    const int jq  = 2 * (lane & 3);

    for (int t = t0; t < tend; t++) {
        uint32_t nb  = sb + STG_NX(t & 1);
        uint32_t knb = sb + STG_KN(t & 1);
        CP_WAIT1();
        __syncthreads();

        // ---- phase 1: S = Q.K^T, exp, fold key norm, pack ----
        uint32_t pk[32];
        #pragma unroll
        for (int g = 0; g < 8; g++) {
            float s0[4] = {0, 0, 0, 0}, s1[4] = {0, 0, 0, 0};
            int krow = g * 16 + kg2 * 8 + klr;
            #pragma unroll
            for (int kk = 0; kk < 8; kk++) {
                uint32_t b[4];
                ldsm4(b, nb + toff(krow, 2 * kk + kg1));
                mma16816(s0, q[kk], b[0], b[1]);
                mma16816(s1, q[kk], b[2], b[3]);
            }
            float e00 = expp(s0[0]), e01 = expp(s0[1]);
            float e02 = expp(s0[2]), e03 = expp(s0[3]);
            float e10 = expp(s1[0]), e11 = expp(s1[1]);
            float e12 = expp(s1[2]), e13 = expp(s1[3]);
            den0 += e00 + e01 + e10 + e11;
            den1 += e02 + e03 + e12 + e13;
            float2 kn01, kn89;
            asm("ld.shared.v2.f32 {%0,%1}, [%2];" : "=f"(kn01.x), "=f"(kn01.y)
                : "r"(knb + (g * 16 + jq) * 4));
            asm("ld.shared.v2.f32 {%0,%1}, [%2];" : "=f"(kn89.x), "=f"(kn89.y)
                : "r"(knb + (g * 16 + 8 + jq) * 4));
            pk[4 * g + 0] = packbf(e00 * kn01.x, e01 * kn01.y);
            pk[4 * g + 1] = packbf(e02 * kn01.x, e03 * kn01.y);
            pk[4 * g + 2] = packbf(e10 * kn89.x, e11 * kn89.y);
            pk[4 * g + 3] = packbf(e12 * kn89.x, e13 * kn89.y);
        }

        // ---- phase 2: O += P . NX (trans loads on the SAME nx tile) ----
        #pragma unroll
        for (int kk = 0; kk < 8; kk++) {
            int vrow = kk * 16 + kg1 * 8 + klr;
            #pragma unroll
            for (int dg = 0; dg < 8; dg++) {
                uint32_t v[4];
                ldsm4t(v, nb + toff(vrow, 2 * dg + kg2));
                mma16816(o[2 * dg],     &pk[4 * kk], v[0], v[1]);
                mma16816(o[2 * dg + 1], &pk[4 * kk], v[2], v[3]);
            }
        }

        __syncthreads();
        prefetch_tile(t + 2, tend, sb, tid);
    }

    // ---- write partials: den (quad-reduced) + O frags ----
    den0 += __shfl_xor_sync(0xffffffffu, den0, 1);
    den0 += __shfl_xor_sync(0xffffffffu, den0, 2);
    den1 += __shfl_xor_sync(0xffffffffu, den1, 1);
    den1 += __shfl_xor_sync(0xffffffffu, den1, 2);

    const int ra = i0 + wid * 16 + (lane >> 2);
    if ((lane & 3) == 0) {
        g_dpart[half][ra]     = den0;
        g_dpart[half][ra + 8] = den1;
    }
    #pragma unroll
    for (int j = 0; j < 16; j++) {
        int col = 8 * j + jq;
        *(float2*)&g_opart[half][ra][col]     = make_float2(o[j][0], o[j][1]);
        *(float2*)&g_opart[half][ra + 8][col] = make_float2(o[j][2], o[j][3]);
    }
}

// ---------------------------------------------------------------------------
// Epilogue: combine KSPLIT partials, y = 1.5x - 0.5*O/den, LayerNorm.
// ---------------------------------------------------------------------------
__global__ __launch_bounds__(256)
void ln_kernel(const float* __restrict__ x,
               const float* __restrict__ gamma,
               const float* __restrict__ beta,
               float* __restrict__ out) {
    const int row  = blockIdx.x * 8 + (threadIdx.x >> 5);
    const int lane = threadIdx.x & 31;
    const int c    = lane * 4;

    float4 oa = *(const float4*)&g_opart[0][row][c];
    float den = g_dpart[0][row];
    #pragma unroll
    for (int h = 1; h < KSPLIT; h++) {
        float4 ob = *(const float4*)&g_opart[h][row][c];
        oa.x += ob.x; oa.y += ob.y; oa.z += ob.z; oa.w += ob.w;
        den += g_dpart[h][row];
    }
    const float inv = 0.5f / den;   // folds SCALE=-0.5
    float4 xv = *(const float4*)(x + (size_t)row * DD + c);

    float y0 = fmaf(1.5f, xv.x, -oa.x * inv);
    float y1 = fmaf(1.5f, xv.y, -oa.y * inv);
    float y2 = fmaf(1.5f, xv.z, -oa.z * inv);
    float y3 = fmaf(1.5f, xv.w, -oa.w * inv);

    float s1 = y0 + y1 + y2 + y3;
    float s2 = fmaf(y0, y0, fmaf(y1, y1, fmaf(y2, y2, y3 * y3)));
    #pragma unroll
    for (int o = 16; o; o >>= 1) {
        s1 += __shfl_xor_sync(0xffffffffu, s1, o);
        s2 += __shfl_xor_sync(0xffffffffu, s2, o);
    }
    const float mu   = s1 * (1.0f / DD);
    const float var  = s2 * (1.0f / DD) - mu * mu;
    const float rstd = rsqrtf(var + 1e-5f);

    float4 gm = *(const float4*)(gamma + c);
    float4 bt = *(const float4*)(beta + c);
    float4 r;
    r.x = fmaf((y0 - mu) * rstd, gm.x, bt.x);
    r.y = fmaf((y1 - mu) * rstd, gm.y, bt.y);
    r.z = fmaf((y2 - mu) * rstd, gm.z, bt.z);
    r.w = fmaf((y3 - mu) * rstd, gm.w, bt.w);
    *(float4*)(out + (size_t)row * DD + c) = r;
}

// ---------------------------------------------------------------------------
extern "C" void kernel_launch(void* const* d_in, const int* in_sizes, int n_in,
                              void* d_out, int out_size) {
    const float* x     = (const float*)d_in[0];
    const float* gamma = (const float*)d_in[1];
    const float* beta  = (const float*)d_in[2];
    float* out = (float*)d_out;

    prep_kernel<<<NROWS / 8, 256>>>(x);

    cudaFuncSetAttribute(attn_kernel,
                         cudaFuncAttributeMaxDynamicSharedMemorySize, SMEM_BYTES);
    attn_kernel<<<(NROWS / BM) * KSPLIT, NTHREADS, SMEM_BYTES>>>();

    ln_kernel<<<NROWS / 8, 256>>>(x, gamma, beta, out);
}